// round 2
// baseline (speedup 1.0000x reference)
#include <cuda_runtime.h>

// GooLayer: B=2, M=64, D=64, T=8192
// Coupled state (no vel cancellation):
//   g_t  = f_t + ki*h_t                     (off critical path)
//   acc  = g_t - ki*pos_{t-1}
//   vs_t = vs_{t-1}*DAMP + acc              (vs = vel/DAMP carried pre-damp)
//   pos  = pos + vs_t*DAMP
//   vel_t*gain = vs_t * (DAMP*gain)
//   tanh via ex2+rcp: tanh(x) = 1 - 2/(2^(x*2*log2e) + 1)   (~1e-7 abs err)

#define BB 2
#define MM 64
#define DD 64
#define TT 8192
#define DAMP 0.9998f
#define WIN 32
#define NW (TT / WIN)   // 256 windows
#define NV (WIN / 4)    // 8 float4 per window

// Per-half partial sums: [half][ bm*T + t ]
__device__ float4 g_partial[2][(BB * MM * TT) / 4];

__device__ __forceinline__ float ex2_fast(float x) {
    float y;
    asm("ex2.approx.f32 %0, %1;" : "=f"(y) : "f"(x));
    return y;
}
__device__ __forceinline__ float rcp_fast(float x) {
    float y;
    asm("rcp.approx.f32 %0, %1;" : "=f"(y) : "f"(x));
    return y;
}

__global__ __launch_bounds__(64, 1)
void goo_scan_kernel(const float* __restrict__ forces,
                     const float* __restrict__ home,
                     const float* __restrict__ mic,
                     const float* __restrict__ masses,
                     const float* __restrict__ tensions,
                     const float* __restrict__ gains)
{
    // One warp per (bm, D-half). 128 blocks x 2 warps = 256 warp-units.
    __shared__ float sh[2][32][33];

    const int tid  = threadIdx.x;
    const int wid  = tid >> 5;
    const int lane = tid & 31;
    const int u    = blockIdx.x * 2 + wid;   // 0..255
    const int bm   = u >> 1;                 // 0..127  (= b*M + m)
    const int half = u & 1;
    const int m    = bm & (MM - 1);
    const int d    = half * 32 + lane;

    const float ki   = tensions[m * DD + d] / masses[m];
    const float nki  = -ki;
    // tanh argument scale folded with the 2*log2(e) of the ex2 formulation
    const float karg = gains[m] * (DAMP * 2.0f * 1.4426950408889634f);
    const float micv = mic[bm * DD + d];
    const float m2mic = -2.0f * micv;

    const size_t base = ((size_t)bm * DD + d) * TT;
    const float4* __restrict__ f4p = (const float4*)(forces + base);
    const float4* __restrict__ h4p = (const float4*)(home + base);

    float* rpart = (float*)g_partial[half] + (size_t)bm * TT;
    float (*tile)[33] = sh[wid];

    float pos = 0.0f, vs = 0.0f;

    // Double-buffered window loads (prefetch distance ~1.5-2 windows > DRAM lat)
    float4 fb[2][NV], hb[2][NV];
    #pragma unroll
    for (int i = 0; i < NV; i++) { fb[0][i] = __ldcs(f4p + i);      hb[0][i] = __ldcs(h4p + i); }
    #pragma unroll
    for (int i = 0; i < NV; i++) { fb[1][i] = __ldcs(f4p + NV + i); hb[1][i] = __ldcs(h4p + NV + i); }

    for (int w = 0; w < NW; w += 2) {
        #pragma unroll
        for (int s = 0; s < 2; s++) {
            const int wi = w + s;

            // ---- compute one 32-step window ----
            #pragma unroll
            for (int i = 0; i < NV; i++) {
                float4 fv = fb[s][i];
                float4 hv = hb[s][i];
                #pragma unroll
                for (int j = 0; j < 4; j++) {
                    float f = (&fv.x)[j];
                    float h = (&hv.x)[j];
                    float g   = fmaf(ki, h, f);          // off critical path
                    float acc = fmaf(nki, pos, g);       // FFMA (chain)
                    vs  = fmaf(vs, DAMP, acc);           // FFMA-imm (chain)
                    pos = fmaf(vs, DAMP, pos);           // FFMA-imm (chain)
                    // tanh(vs*DAMP*gain) = 1 - 2/(ex2(vs*karg)+1)
                    float a  = vs * karg;
                    float e  = ex2_fast(a);              // MUFU.EX2
                    float dn = e + 1.0f;
                    float r  = rcp_fast(dn);             // MUFU.RCP
                    tile[4 * i + j][lane] = fmaf(r, m2mic, micv);  // tanh*mic
                }
            }
            __syncwarp();

            // ---- transpose-reduce: lane L sums time-slot L across 32 d-lanes ----
            float a0 = 0.f, a1 = 0.f, a2 = 0.f, a3 = 0.f;
            #pragma unroll
            for (int j = 0; j < 32; j += 4) {
                a0 += tile[lane][j + 0];
                a1 += tile[lane][j + 1];
                a2 += tile[lane][j + 2];
                a3 += tile[lane][j + 3];
            }
            rpart[wi * WIN + lane] = (a0 + a1) + (a2 + a3);  // coalesced STG.32
            __syncwarp();

            // ---- prefetch window wi+2 into this slot ----
            if (wi + 2 < NW) {
                const int o = (wi + 2) * NV;
                #pragma unroll
                for (int i = 0; i < NV; i++) {
                    fb[s][i] = __ldcs(f4p + o + i);
                    hb[s][i] = __ldcs(h4p + o + i);
                }
            }
        }
    }
}

// Sum the two D-half partials into d_out (writes every output element).
__global__ __launch_bounds__(512, 2)
void goo_combine_kernel(float4* __restrict__ out)
{
    int i = blockIdx.x * blockDim.x + threadIdx.x;  // 0 .. 262143
    float4 a = g_partial[0][i];
    float4 b = g_partial[1][i];
    out[i] = make_float4(a.x + b.x, a.y + b.y, a.z + b.z, a.w + b.w);
}

extern "C" void kernel_launch(void* const* d_in, const int* in_sizes, int n_in,
                              void* d_out, int out_size)
{
    const float* forces   = (const float*)d_in[0];
    const float* home     = (const float*)d_in[1];
    const float* mic      = (const float*)d_in[2];
    const float* masses   = (const float*)d_in[3];
    const float* tensions = (const float*)d_in[4];
    const float* gains    = (const float*)d_in[5];

    goo_scan_kernel<<<128, 64>>>(forces, home, mic, masses, tensions, gains);

    // (B*M*T)/4 float4 elements = 262144 -> 512 blocks x 512 threads
    goo_combine_kernel<<<512, 512>>>((float4*)d_out);
}